// round 1
// baseline (speedup 1.0000x reference)
#include <cuda_runtime.h>
#include <cstdint>

#define BB   2
#define SS   2048
#define HH   16
#define DHH  64
#define DMM  1024

// Scratch (allocation-free rule: __device__ globals)
__device__ float g_Q[(size_t)BB * HH * SS * DHH];
__device__ float g_K[(size_t)BB * HH * SS * DHH];
__device__ float g_V[(size_t)BB * HH * SS * DHH];
__device__ float g_ctx[(size_t)BB * SS * DMM];

// ---------------------------------------------------------------------------
// Tiled fp32 GEMM: C[M=4096, N=1024] = A @ W + bias
// 128x128 tile, 256 threads, 8x8 microtile, k-step 16.
// SCATTER=true writes C[m][n] into [B,H,S,Dh] layout (head split).
// ---------------------------------------------------------------------------
template <bool SCATTER>
__device__ __forceinline__ void gemm_body(const float* __restrict__ A,
                                          const float* __restrict__ W,
                                          const float* __restrict__ bias,
                                          float* __restrict__ out) {
    __shared__ float As[16 * 132];  // transposed: As[k][m], padded stride 132
    __shared__ float Bs[16 * 132];  // Bs[k][n]

    const int M0 = blockIdx.x * 128;
    const int N0 = blockIdx.y * 128;
    const int tid = threadIdx.x;
    const int ty = tid >> 4;   // 0..15 -> rows m = M0 + ty*8 ..
    const int tx = tid & 15;   // 0..15 -> cols n = N0 + tx*8 ..

    float acc[8][8];
#pragma unroll
    for (int i = 0; i < 8; i++)
#pragma unroll
        for (int j = 0; j < 8; j++) acc[i][j] = 0.f;

    for (int kt = 0; kt < DMM; kt += 16) {
        // Load A tile 128x16, store transposed As[k][m]
#pragma unroll
        for (int i = 0; i < 2; i++) {
            int f = tid + i * 256;     // 0..511 float4s
            int row = f >> 2;          // 0..127
            int c4 = f & 3;            // 0..3
            float4 v = *(const float4*)&A[(size_t)(M0 + row) * DMM + kt + c4 * 4];
            As[(c4 * 4 + 0) * 132 + row] = v.x;
            As[(c4 * 4 + 1) * 132 + row] = v.y;
            As[(c4 * 4 + 2) * 132 + row] = v.z;
            As[(c4 * 4 + 3) * 132 + row] = v.w;
        }
        // Load W tile 16x128 row-major
#pragma unroll
        for (int i = 0; i < 2; i++) {
            int f = tid + i * 256;
            int kr = f >> 5;           // 0..15
            int c4 = f & 31;           // 0..31
            *(float4*)&Bs[kr * 132 + c4 * 4] =
                *(const float4*)&W[(size_t)(kt + kr) * DMM + N0 + c4 * 4];
        }
        __syncthreads();

#pragma unroll
        for (int kk = 0; kk < 16; kk++) {
            float a[8], b[8];
            *(float4*)&a[0] = *(const float4*)&As[kk * 132 + ty * 8];
            *(float4*)&a[4] = *(const float4*)&As[kk * 132 + ty * 8 + 4];
            *(float4*)&b[0] = *(const float4*)&Bs[kk * 132 + tx * 8];
            *(float4*)&b[4] = *(const float4*)&Bs[kk * 132 + tx * 8 + 4];
#pragma unroll
            for (int i = 0; i < 8; i++)
#pragma unroll
                for (int j = 0; j < 8; j++)
                    acc[i][j] = fmaf(a[i], b[j], acc[i][j]);
        }
        __syncthreads();
    }

#pragma unroll
    for (int i = 0; i < 8; i++) {
        int mm = M0 + ty * 8 + i;
#pragma unroll
        for (int j = 0; j < 8; j++) {
            int n = N0 + tx * 8 + j;
            float v = acc[i][j] + bias[n];
            if (SCATTER) {
                int bidx = mm >> 11;          // / 2048
                int srow = mm & (SS - 1);
                int hh = n >> 6;              // / 64
                int dd = n & 63;
                out[((size_t)(bidx * HH + hh) * SS + srow) * DHH + dd] = v;
            } else {
                out[(size_t)mm * DMM + n] = v;
            }
        }
    }
}

__global__ void __launch_bounds__(256)
qkv_kernel(const float* __restrict__ x,
           const float* __restrict__ Wq, const float* __restrict__ bq,
           const float* __restrict__ Wk, const float* __restrict__ bk,
           const float* __restrict__ Wv, const float* __restrict__ bv) {
    int z = blockIdx.z;
    const float* W = (z == 0) ? Wq : (z == 1) ? Wk : Wv;
    const float* bias = (z == 0) ? bq : (z == 1) ? bk : bv;
    float* out = (z == 0) ? g_Q : (z == 1) ? g_K : g_V;
    gemm_body<true>(x, W, bias, out);
}

__global__ void __launch_bounds__(256)
oproj_kernel(const float* __restrict__ Wo, const float* __restrict__ bo,
             float* __restrict__ out) {
    gemm_body<false>(g_ctx, Wo, bo, out);
}

// ---------------------------------------------------------------------------
// Flash-style causal attention with additive pos_bias.
// One CTA per (b, h, 64-row q tile). 256 threads as 16(ty:rows)x16(tx:cols),
// 4x4 microtile. Online softmax over 64-key tiles; diagonal tile masked
// element-wise to exactly -1e9 (matches reference where(mask==0, -1e9, .)).
// ---------------------------------------------------------------------------
#define AST 68  // padded smem row stride (floats), keeps float4 alignment

__global__ void __launch_bounds__(256)
attn_kernel(const float* __restrict__ pb_all) {
    extern __shared__ float sm[];
    float* Qs = sm;                 // [d][r]  (64 x AST)
    float* Ks = Qs + 64 * AST;      // [d][j]
    float* Vs = Ks + 64 * AST;      // [j][d]
    float* Ps = Vs + 64 * AST;      // [j][r]

    const int qt = (int)gridDim.x - 1 - (int)blockIdx.x;  // longest first
    const int h = blockIdx.y;
    const int bb = blockIdx.z;
    const int q0 = qt * 64;

    const size_t hoff = (size_t)(bb * HH + h) * SS * DHH;
    const float* Qg = g_Q + hoff;
    const float* Kg = g_K + hoff;
    const float* Vg = g_V + hoff;
    const float* pb = pb_all + (size_t)h * SS * SS;

    const int tid = threadIdx.x;
    const int ty = tid >> 4;   // query rows r = ty*4 .. +3
    const int tx = tid & 15;   // key cols  j = tx*4 .. +3

    // Load Q tile transposed (coalesced global, broadcast-friendly smem)
    for (int idx = tid; idx < 64 * DHH; idx += 256) {
        int r = idx >> 6, d = idx & 63;
        Qs[d * AST + r] = Qg[(size_t)(q0 + r) * DHH + d];
    }

    float m[4], l[4], o[4][4];
#pragma unroll
    for (int i = 0; i < 4; i++) {
        m[i] = -3.0e38f;
        l[i] = 0.f;
#pragma unroll
        for (int c = 0; c < 4; c++) o[i][c] = 0.f;
    }

    for (int kt = 0; kt <= qt; kt++) {
        const int k0 = kt * 64;
        __syncthreads();  // previous PV done (and Q load visible on iter 0)
        for (int idx = tid; idx < 64 * DHH; idx += 256) {
            int r = idx >> 6, d = idx & 63;
            Ks[d * AST + r] = Kg[(size_t)(k0 + r) * DHH + d];
            Vs[r * AST + d] = Vg[(size_t)(k0 + r) * DHH + d];
        }
        __syncthreads();

        // stage pos_bias (coalesced float4 per row)
        float4 brow[4];
#pragma unroll
        for (int i = 0; i < 4; i++)
            brow[i] = *(const float4*)&pb[(size_t)(q0 + ty * 4 + i) * SS + k0 + tx * 4];

        // scores: 4x4 dot over d=64
        float s[4][4];
#pragma unroll
        for (int i = 0; i < 4; i++)
#pragma unroll
            for (int j = 0; j < 4; j++) s[i][j] = 0.f;

#pragma unroll
        for (int d = 0; d < 64; d++) {
            float4 qv = *(const float4*)&Qs[d * AST + ty * 4];
            float4 kv = *(const float4*)&Ks[d * AST + tx * 4];
            float qa[4] = {qv.x, qv.y, qv.z, qv.w};
            float ka[4] = {kv.x, kv.y, kv.z, kv.w};
#pragma unroll
            for (int i = 0; i < 4; i++)
#pragma unroll
                for (int j = 0; j < 4; j++)
                    s[i][j] = fmaf(qa[i], ka[j], s[i][j]);
        }

        // scale + bias
#pragma unroll
        for (int i = 0; i < 4; i++) {
            s[i][0] = s[i][0] * 0.125f + brow[i].x;
            s[i][1] = s[i][1] * 0.125f + brow[i].y;
            s[i][2] = s[i][2] * 0.125f + brow[i].z;
            s[i][3] = s[i][3] * 0.125f + brow[i].w;
        }
        // causal mask — only diagonal tile can violate
        if (kt == qt) {
#pragma unroll
            for (int i = 0; i < 4; i++)
#pragma unroll
                for (int j = 0; j < 4; j++)
                    if (tx * 4 + j > ty * 4 + i) s[i][j] = -1.0e9f;
        }

        // online softmax per row (16 tx lanes of same ty reduce via shfl_xor,
        // partners stay within the same 16-lane half-warp => same ty)
#pragma unroll
        for (int i = 0; i < 4; i++) {
            float tmax = fmaxf(fmaxf(s[i][0], s[i][1]), fmaxf(s[i][2], s[i][3]));
#pragma unroll
            for (int off = 8; off >= 1; off >>= 1)
                tmax = fmaxf(tmax, __shfl_xor_sync(0xffffffffu, tmax, off));
            float mn = fmaxf(m[i], tmax);
            float corr = __expf(m[i] - mn);
            m[i] = mn;
            l[i] *= corr;
#pragma unroll
            for (int c = 0; c < 4; c++) o[i][c] *= corr;
            float psum = 0.f;
#pragma unroll
            for (int j = 0; j < 4; j++) {
                float p = __expf(s[i][j] - mn);
                s[i][j] = p;
                psum += p;
            }
#pragma unroll
            for (int off = 8; off >= 1; off >>= 1)
                psum += __shfl_xor_sync(0xffffffffu, psum, off);
            l[i] += psum;
        }

        // write P transposed for the PV pass
#pragma unroll
        for (int i = 0; i < 4; i++)
#pragma unroll
            for (int j = 0; j < 4; j++)
                Ps[(tx * 4 + j) * AST + ty * 4 + i] = s[i][j];
        __syncthreads();

        // O += P @ V  (thread owns rows ty*4.., dims tx*4..)
#pragma unroll 8
        for (int j = 0; j < 64; j++) {
            float4 p4 = *(const float4*)&Ps[j * AST + ty * 4];
            float4 v4 = *(const float4*)&Vs[j * AST + tx * 4];
            float pa[4] = {p4.x, p4.y, p4.z, p4.w};
            float va[4] = {v4.x, v4.y, v4.z, v4.w};
#pragma unroll
            for (int i = 0; i < 4; i++)
#pragma unroll
                for (int c = 0; c < 4; c++)
                    o[i][c] = fmaf(pa[i], va[c], o[i][c]);
        }
    }

    // epilogue: normalized context in [B, S, D_MODEL] layout (merge heads)
    float* ctx = g_ctx + (size_t)bb * SS * DMM;
#pragma unroll
    for (int i = 0; i < 4; i++) {
        float inv = 1.f / l[i];
#pragma unroll
        for (int c = 0; c < 4; c++)
            ctx[(size_t)(q0 + ty * 4 + i) * DMM + h * DHH + tx * 4 + c] = o[i][c] * inv;
    }
}

// ---------------------------------------------------------------------------
// Launch
// ---------------------------------------------------------------------------
extern "C" void kernel_launch(void* const* d_in, const int* in_sizes, int n_in,
                              void* d_out, int out_size) {
    const float* x  = (const float*)d_in[0];
    // d_in[1] = mask: deterministic causal tril -> applied analytically
    const float* Wq = (const float*)d_in[2];
    const float* bq = (const float*)d_in[3];
    const float* Wk = (const float*)d_in[4];
    const float* bk = (const float*)d_in[5];
    const float* Wv = (const float*)d_in[6];
    const float* bv = (const float*)d_in[7];
    const float* Wo = (const float*)d_in[8];
    const float* bo = (const float*)d_in[9];
    const float* pb = (const float*)d_in[10];

    const int smem_attn = 4 * 64 * AST * sizeof(float);  // 69632 B
    cudaFuncSetAttribute(attn_kernel, cudaFuncAttributeMaxDynamicSharedMemorySize,
                         smem_attn);

    // 1) fused QKV projections: M=4096 (32 tiles) x N=1024 (8 tiles) x {q,k,v}
    qkv_kernel<<<dim3(32, 8, 3), 256>>>(x, Wq, bq, Wk, bk, Wv, bv);

    // 2) causal attention + pos_bias: (q-tiles=32, heads=16, batch=2)
    attn_kernel<<<dim3(32, 16, 2), 256, smem_attn>>>(pb);

    // 3) output projection -> d_out
    oproj_kernel<<<dim3(32, 8, 1), 256>>>(Wo, bo, (float*)d_out);
}